// round 2
// baseline (speedup 1.0000x reference)
#include <cuda_runtime.h>

#define BB 8
#define NN 2048
#define MM 2048
#define DIN 256
#define EE 128
#define LALPHA 0.01f
#define NCHUNK 32
#define CHUNK 64            // MM / NCHUNK

// ---------------- scratch (device globals; no allocation allowed) ----------------
__device__ float g_v1[DIN], g_v2[DIN];
__device__ float g_att2[BB * MM];
__device__ float g_E1p[BB * NN], g_E1n[BB * NN], g_key[BB * NN];   // key = -att1
__device__ float g_F2p[BB * MM], g_F2n[BB * MM];
__device__ float g_Wh2[BB * MM * EE];
__device__ float g_sortv[BB * MM];
__device__ int   g_sortidx[BB * MM];
__device__ float g_chP[BB * NCHUNK * EE], g_chN[BB * NCHUNK * EE];
__device__ float g_chPs[BB * NCHUNK], g_chNs[BB * NCHUNK];
__device__ float g_offP[BB * NCHUNK * EE], g_offN[BB * NCHUNK * EE];
__device__ float g_offPs[BB * NCHUNK], g_offNs[BB * NCHUNK];
__device__ float g_sufP[BB * (MM + 1) * EE];   // suffix sums of F2p*Wh2 in sorted order
__device__ float g_preN[BB * (MM + 1) * EE];   // prefix sums of F2n*Wh2 in sorted order
__device__ float g_sufPs[BB * (MM + 1)], g_preNs[BB * (MM + 1)];
__device__ float g_c1[BB * NN], g_c2[BB * NN]; // E1p/S, E1n/S per row

// ---------------- 1. v1 = W1 @ a1_top, v2 = W1 @ a1_bot ----------------
__global__ void k_v(const float* __restrict__ W1, const float* __restrict__ a1) {
    int d = threadIdx.x;   // 0..255
    float s1 = 0.f, s2 = 0.f;
    #pragma unroll 8
    for (int e = 0; e < EE; e++) {
        float w = W1[d * EE + e];
        s1 += w * a1[e];
        s2 += w * a1[EE + e];
    }
    g_v1[d] = s1;
    g_v2[d] = s2;
}

// ---------------- 2. att1 / att2 dots + exp factors (one warp per row) ----------------
__global__ void k_att(const float* __restrict__ in1, const float* __restrict__ in2,
                      const float* __restrict__ mask) {
    int w    = (blockIdx.x * blockDim.x + threadIdx.x) >> 5;
    int lane = threadIdx.x & 31;
    bool second = (w >= BB * NN);
    int row = second ? (w - BB * NN) : w;
    const float* src = second ? in2 : in1;
    const float* v   = second ? g_v2 : g_v1;
    const float4* p  = (const float4*)(src + (size_t)row * DIN);
    const float4* v4 = (const float4*)v;
    float acc = 0.f;
    #pragma unroll
    for (int i = 0; i < 2; i++) {
        float4 x  = p[lane + 32 * i];
        float4 vv = v4[lane + 32 * i];
        acc += x.x * vv.x + x.y * vv.y + x.z * vv.z + x.w * vv.w;
    }
    #pragma unroll
    for (int o = 16; o > 0; o >>= 1) acc += __shfl_xor_sync(0xffffffffu, acc, o);
    if (lane == 0) {
        if (!second) {
            g_E1p[row] = expf(acc);
            g_E1n[row] = expf(LALPHA * acc);
            g_key[row] = -acc;
        } else {
            int b = row / MM, m = row % MM;
            float mk = mask[b * MM + m];
            g_att2[row] = acc;
            g_F2p[row] = expf(acc + mk);
            g_F2n[row] = expf(LALPHA * acc + mk);
        }
    }
}

// ---------------- 3. Wh2 = input2 @ W1 (fp32 tiled GEMM, 64-row tiles) ----------------
__global__ void __launch_bounds__(256) k_wh2(const float* __restrict__ in2,
                                             const float* __restrict__ W1) {
    __shared__ float As[64 * 32];
    __shared__ float Bs[32 * 128];
    int tid = threadIdx.x;
    int tx = tid & 31;    // column group -> cols tx*4..tx*4+3
    int ty = tid >> 5;    // row group   -> rows ty*8..ty*8+7
    int row0 = blockIdx.x * 64;
    float acc[8][4];
    #pragma unroll
    for (int r = 0; r < 8; r++)
        #pragma unroll
        for (int c = 0; c < 4; c++) acc[r][c] = 0.f;

    for (int k0 = 0; k0 < DIN; k0 += 32) {
        // Load A tile: 64 rows x 32 K = 512 float4
        #pragma unroll
        for (int i = tid; i < 512; i += 256) {
            int r = i >> 3, kq = i & 7;
            ((float4*)As)[i] = *(const float4*)(in2 + (size_t)(row0 + r) * DIN + k0 + kq * 4);
        }
        // Load B tile: 32 K x 128 E = 1024 float4
        #pragma unroll
        for (int i = tid; i < 1024; i += 256) {
            ((float4*)Bs)[i] = ((const float4*)(W1 + (size_t)k0 * EE))[i];
        }
        __syncthreads();
        #pragma unroll
        for (int kk = 0; kk < 32; kk++) {
            float4 b4 = ((float4*)Bs)[kk * 32 + tx];
            #pragma unroll
            for (int r = 0; r < 8; r++) {
                float a = As[(ty * 8 + r) * 32 + kk];
                acc[r][0] += a * b4.x;
                acc[r][1] += a * b4.y;
                acc[r][2] += a * b4.z;
                acc[r][3] += a * b4.w;
            }
        }
        __syncthreads();
    }
    #pragma unroll
    for (int r = 0; r < 8; r++) {
        int row = row0 + ty * 8 + r;
        float4 o = make_float4(acc[r][0], acc[r][1], acc[r][2], acc[r][3]);
        *(float4*)(g_Wh2 + (size_t)row * EE + tx * 4) = o;
    }
}

// ---------------- 4. per-batch bitonic sort of att2 (with index) ----------------
__global__ void __launch_bounds__(1024) k_sort() {
    __shared__ float v[MM];
    __shared__ int   ix[MM];
    int b = blockIdx.x;
    for (int i = threadIdx.x; i < MM; i += blockDim.x) { v[i] = g_att2[b * MM + i]; ix[i] = i; }
    __syncthreads();
    for (int k = 2; k <= MM; k <<= 1) {
        for (int j = k >> 1; j > 0; j >>= 1) {
            for (int t = threadIdx.x; t < MM; t += blockDim.x) {
                int p = t ^ j;
                if (p > t) {
                    bool up = ((t & k) == 0);
                    float a = v[t], c = v[p];
                    if ((a > c) == up) {
                        v[t] = c; v[p] = a;
                        int tmp = ix[t]; ix[t] = ix[p]; ix[p] = tmp;
                    }
                }
            }
            __syncthreads();
        }
    }
    for (int i = threadIdx.x; i < MM; i += blockDim.x) {
        g_sortv[b * MM + i] = v[i];
        g_sortidx[b * MM + i] = ix[i];
    }
}

// ---------------- 5a. chunk partial sums (sorted order) ----------------
__global__ void k_chunksum() {
    int b = blockIdx.y, c = blockIdx.x, e = threadIdx.x;
    int base = b * MM + c * CHUNK;
    double aP = 0.0, aN = 0.0, sP = 0.0, sN = 0.0;
    for (int j = 0; j < CHUNK; j++) {
        int m = g_sortidx[base + j];
        float fp = g_F2p[b * MM + m];
        float fn = g_F2n[b * MM + m];
        float w = g_Wh2[(size_t)(b * MM + m) * EE + e];
        aP += (double)fp * w;
        aN += (double)fn * w;
        sP += fp;
        sN += fn;
    }
    g_chP[(b * NCHUNK + c) * EE + e] = (float)aP;
    g_chN[(b * NCHUNK + c) * EE + e] = (float)aN;
    if (e == 0) { g_chPs[b * NCHUNK + c] = (float)sP; g_chNs[b * NCHUNK + c] = (float)sN; }
}

// ---------------- 5b. chunk-level offsets (forward for N, reverse for P) ----------------
__global__ void k_offsets() {
    int b = blockIdx.x, e = threadIdx.x;
    double run = 0.0;
    for (int c = 0; c < NCHUNK; c++) {
        g_offN[(b * NCHUNK + c) * EE + e] = (float)run;
        run += g_chN[(b * NCHUNK + c) * EE + e];
    }
    g_preN[((size_t)b * (MM + 1) + MM) * EE + e] = (float)run;
    double runP = 0.0;
    for (int c = NCHUNK - 1; c >= 0; c--) {
        g_offP[(b * NCHUNK + c) * EE + e] = (float)runP;
        runP += g_chP[(b * NCHUNK + c) * EE + e];
    }
    g_sufP[((size_t)b * (MM + 1) + MM) * EE + e] = 0.f;
    if (e == 0) {
        double r = 0.0;
        for (int c = 0; c < NCHUNK; c++) { g_offNs[b * NCHUNK + c] = (float)r; r += g_chNs[b * NCHUNK + c]; }
        g_preNs[b * (MM + 1) + MM] = (float)r;
        double rp = 0.0;
        for (int c = NCHUNK - 1; c >= 0; c--) { g_offPs[b * NCHUNK + c] = (float)rp; rp += g_chPs[b * NCHUNK + c]; }
        g_sufPs[b * (MM + 1) + MM] = 0.f;
    }
}

// ---------------- 5c. fine-grained prefix (N) and suffix (P) sums ----------------
__global__ void k_scan() {
    int b = blockIdx.y, c = blockIdx.x, e = threadIdx.x;
    int base = b * MM + c * CHUNK;
    double runN  = (double)g_offN[(b * NCHUNK + c) * EE + e];
    double runNs = (double)g_offNs[b * NCHUNK + c];
    for (int j = 0; j < CHUNK; j++) {
        int k = c * CHUNK + j;
        g_preN[((size_t)b * (MM + 1) + k) * EE + e] = (float)runN;
        if (e == 0) g_preNs[b * (MM + 1) + k] = (float)runNs;
        int m = g_sortidx[base + j];
        float fn = g_F2n[b * MM + m];
        float w = g_Wh2[(size_t)(b * MM + m) * EE + e];
        runN += (double)fn * w;
        runNs += fn;
    }
    double runP  = (double)g_offP[(b * NCHUNK + c) * EE + e];
    double runPs = (double)g_offPs[b * NCHUNK + c];
    for (int j = CHUNK - 1; j >= 0; j--) {
        int k = c * CHUNK + j;
        int m = g_sortidx[base + j];
        float fp = g_F2p[b * MM + m];
        float w = g_Wh2[(size_t)(b * MM + m) * EE + e];
        runP += (double)fp * w;
        runPs += fp;
        g_sufP[((size_t)b * (MM + 1) + k) * EE + e] = (float)runP;
        if (e == 0) g_sufPs[b * (MM + 1) + k] = (float)runPs;
    }
}

// ---------------- 6. per-row rank (single-thread binary search) + context + 1/S ----------------
__global__ void __launch_bounds__(EE) k_rank(float* __restrict__ out_ctx) {
    int row = blockIdx.x;          // 0 .. B*N-1
    int b = row >> 11;             // row / 2048
    int e = threadIdx.x;           // 0..127
    __shared__ int sk;
    if (e == 0) {
        float key = g_key[row];    // -att1
        const float* sv = g_sortv + b * MM;
        int lo = 0, hi = MM;       // first index with sv[idx] > key
        while (lo < hi) {
            int mid = (lo + hi) >> 1;
            if (sv[mid] > key) hi = mid; else lo = mid + 1;
        }
        sk = lo;
    }
    __syncthreads();
    int k = sk;
    float E1p = g_E1p[row], E1n = g_E1n[row];
    float S = E1p * g_sufPs[b * (MM + 1) + k] + E1n * g_preNs[b * (MM + 1) + k];
    float num = E1p * g_sufP[((size_t)b * (MM + 1) + k) * EE + e]
              + E1n * g_preN[((size_t)b * (MM + 1) + k) * EE + e];
    float invS = 1.f / S;
    out_ctx[(size_t)row * EE + e] = num * invS;
    if (e == 0) { g_c1[row] = E1p * invS; g_c2[row] = E1n * invS; }
}

// ---------------- 7. probs (8 rows per block; store-bound) ----------------
__global__ void __launch_bounds__(512) k_probs(float* __restrict__ out_p) {
    int g = blockIdx.x;            // 0 .. B*N/8 - 1
    int row0 = g * 8;
    int b = row0 >> 11;
    int t = threadIdx.x;           // 0..511, each handles one float4 (4 m's)
    const float4* t4 = (const float4*)(g_att2 + b * MM);
    const float4* p4 = (const float4*)(g_F2p + b * MM);
    const float4* n4 = (const float4*)(g_F2n + b * MM);
    float4 tv = t4[t], pv = p4[t], nv = n4[t];
    #pragma unroll
    for (int r = 0; r < 8; r++) {
        int row = row0 + r;
        float key = g_key[row];
        float c1 = g_c1[row];
        float c2 = g_c2[row];
        float4 o;
        o.x = (tv.x > key) ? c1 * pv.x : c2 * nv.x;
        o.y = (tv.y > key) ? c1 * pv.y : c2 * nv.y;
        o.z = (tv.z > key) ? c1 * pv.z : c2 * nv.z;
        o.w = (tv.w > key) ? c1 * pv.w : c2 * nv.w;
        ((float4*)(out_p + (size_t)row * MM))[t] = o;
    }
}

// ---------------- launch ----------------
extern "C" void kernel_launch(void* const* d_in, const int* in_sizes, int n_in,
                              void* d_out, int out_size) {
    const float* in1  = (const float*)d_in[0];   // (8,2048,256)
    const float* in2  = (const float*)d_in[1];   // (8,2048,256)
    const float* mask = (const float*)d_in[2];   // (8,1,2048)
    const float* W1   = (const float*)d_in[3];   // (256,128)
    const float* a1   = (const float*)d_in[4];   // (256,1)
    float* out = (float*)d_out;
    float* out_ctx   = out;                              // (8,2048,128)
    float* out_probs = out + (size_t)BB * NN * EE;       // (8,2048,2048)

    k_v<<<1, 256>>>(W1, a1);
    k_att<<<4096, 256>>>(in1, in2, mask);
    k_wh2<<<BB * MM / 64, 256>>>(in2, W1);
    k_sort<<<BB, 1024>>>();
    dim3 gc(NCHUNK, BB);
    k_chunksum<<<gc, EE>>>();
    k_offsets<<<BB, EE>>>();
    k_scan<<<gc, EE>>>();
    k_rank<<<BB * NN, EE>>>(out_ctx);
    k_probs<<<BB * NN / 8, 512>>>(out_probs);
}

// round 5
// speedup vs baseline: 1.0808x; 1.0808x over previous
#include <cuda_runtime.h>
#include <cub/cub.cuh>

#define BB 8
#define NN 2048
#define MM 2048
#define DIN 256
#define EE 128
#define LALPHA 0.01f
#define NCHUNK 32
#define CHUNK 64            // MM / NCHUNK

// ---------------- scratch (device globals; no allocation allowed) ----------------
__device__ float g_v1[DIN];
__device__ float g_att2[BB * MM];
__device__ float g_E1p[BB * NN], g_E1n[BB * NN], g_key[BB * NN];   // key = -att1
__device__ float g_F2p[BB * MM], g_F2n[BB * MM];
__device__ float g_Wh2[BB * MM * EE];
__device__ float g_sortv[BB * MM];
__device__ int   g_sortidx[BB * MM];
__device__ float g_chP[BB * NCHUNK * EE], g_chN[BB * NCHUNK * EE];
__device__ float g_chPs[BB * NCHUNK], g_chNs[BB * NCHUNK];
__device__ float g_offP[BB * NCHUNK * EE], g_offN[BB * NCHUNK * EE];
__device__ float g_offPs[BB * NCHUNK], g_offNs[BB * NCHUNK];
__device__ float g_sufP[BB * (MM + 1) * EE];   // suffix sums of F2p*Wh2 in sorted order
__device__ float g_preN[BB * (MM + 1) * EE];   // prefix sums of F2n*Wh2 in sorted order
__device__ float g_sufPs[BB * (MM + 1)], g_preNs[BB * (MM + 1)];

// ---------------- 1. v1 = W1 @ a1_top ----------------
__global__ void k_v(const float* __restrict__ W1, const float* __restrict__ a1) {
    int d = threadIdx.x;   // 0..255
    float s1 = 0.f;
    #pragma unroll 8
    for (int e = 0; e < EE; e++) s1 += W1[d * EE + e] * a1[e];
    g_v1[d] = s1;
}

// ---------------- 2. att1 dot + exp factors for input1 (one warp per row) ----------------
__global__ void __launch_bounds__(256) k_att1(const float* __restrict__ in1) {
    int w    = (blockIdx.x * blockDim.x + threadIdx.x) >> 5;   // 0 .. B*N-1
    int lane = threadIdx.x & 31;
    const float4* p  = (const float4*)(in1 + (size_t)w * DIN);
    const float4* v4 = (const float4*)g_v1;
    float acc = 0.f;
    #pragma unroll
    for (int i = 0; i < 2; i++) {
        float4 x  = p[lane + 32 * i];
        float4 vv = v4[lane + 32 * i];
        acc += x.x * vv.x + x.y * vv.y + x.z * vv.z + x.w * vv.w;
    }
    #pragma unroll
    for (int o = 16; o > 0; o >>= 1) acc += __shfl_xor_sync(0xffffffffu, acc, o);
    if (lane == 0) {
        g_E1p[w] = expf(acc);
        g_E1n[w] = expf(LALPHA * acc);
        g_key[w] = -acc;
    }
}

// ---------------- 3. Wh2 = input2 @ W1 + fused att2/F2p/F2n epilogue ----------------
__global__ void __launch_bounds__(256) k_wh2(const float* __restrict__ in2,
                                             const float* __restrict__ W1,
                                             const float* __restrict__ mask,
                                             const float* __restrict__ a1) {
    __shared__ float As[64 * 32];
    __shared__ float Bs[32 * 128];
    int tid = threadIdx.x;
    int tx = tid & 31;    // column group -> cols tx*4..tx*4+3
    int ty = tid >> 5;    // row group   -> rows ty*8..ty*8+7 (one warp per ty)
    int row0 = blockIdx.x * 64;
    float acc[8][4];
    #pragma unroll
    for (int r = 0; r < 8; r++)
        #pragma unroll
        for (int c = 0; c < 4; c++) acc[r][c] = 0.f;

    for (int k0 = 0; k0 < DIN; k0 += 32) {
        #pragma unroll
        for (int i = tid; i < 512; i += 256) {
            int r = i >> 3, kq = i & 7;
            ((float4*)As)[i] = *(const float4*)(in2 + (size_t)(row0 + r) * DIN + k0 + kq * 4);
        }
        #pragma unroll
        for (int i = tid; i < 1024; i += 256) {
            ((float4*)Bs)[i] = ((const float4*)(W1 + (size_t)k0 * EE))[i];
        }
        __syncthreads();
        #pragma unroll
        for (int kk = 0; kk < 32; kk += 4) {
            float4 b0 = ((float4*)Bs)[(kk + 0) * 32 + tx];
            float4 b1 = ((float4*)Bs)[(kk + 1) * 32 + tx];
            float4 b2 = ((float4*)Bs)[(kk + 2) * 32 + tx];
            float4 b3 = ((float4*)Bs)[(kk + 3) * 32 + tx];
            #pragma unroll
            for (int r = 0; r < 8; r++) {
                float4 a4 = *(float4*)&As[(ty * 8 + r) * 32 + kk];   // warp-broadcast
                acc[r][0] += a4.x * b0.x + a4.y * b1.x + a4.z * b2.x + a4.w * b3.x;
                acc[r][1] += a4.x * b0.y + a4.y * b1.y + a4.z * b2.y + a4.w * b3.y;
                acc[r][2] += a4.x * b0.z + a4.y * b1.z + a4.z * b2.z + a4.w * b3.z;
                acc[r][3] += a4.x * b0.w + a4.y * b1.w + a4.z * b2.w + a4.w * b3.w;
            }
        }
        __syncthreads();
    }
    // epilogue: store Wh2 and compute att2 = Wh2 . a1[128:]
    float4 va = *(const float4*)(a1 + EE + tx * 4);
    #pragma unroll
    for (int r = 0; r < 8; r++) {
        int row = row0 + ty * 8 + r;
        *(float4*)(g_Wh2 + (size_t)row * EE + tx * 4) =
            make_float4(acc[r][0], acc[r][1], acc[r][2], acc[r][3]);
        float part = acc[r][0] * va.x + acc[r][1] * va.y + acc[r][2] * va.z + acc[r][3] * va.w;
        #pragma unroll
        for (int o = 16; o > 0; o >>= 1) part += __shfl_xor_sync(0xffffffffu, part, o);
        if (tx == 0) {
            int b = row >> 11, m = row & (MM - 1);
            float mk = mask[b * MM + m];
            g_att2[row] = part;
            g_F2p[row] = expf(part + mk);
            g_F2n[row] = expf(LALPHA * part + mk);
        }
    }
}

// ---------------- 4. per-batch radix sort of att2 (with index) ----------------
__global__ void __launch_bounds__(512) k_sort() {
    typedef cub::BlockRadixSort<float, 512, 4, int> Sorter;
    __shared__ typename Sorter::TempStorage tmp;
    int b = blockIdx.x;
    float key[4];
    int   val[4];
    #pragma unroll
    for (int i = 0; i < 4; i++) {
        int idx = threadIdx.x * 4 + i;
        key[i] = g_att2[b * MM + idx];
        val[i] = idx;
    }
    Sorter(tmp).Sort(key, val);
    #pragma unroll
    for (int i = 0; i < 4; i++) {
        int idx = threadIdx.x * 4 + i;
        g_sortv[b * MM + idx]   = key[i];
        g_sortidx[b * MM + idx] = val[i];
    }
}

// ---------------- 5a. chunk partial sums (sorted order) ----------------
__global__ void k_chunksum() {
    int b = blockIdx.y, c = blockIdx.x, e = threadIdx.x;
    int base = b * MM + c * CHUNK;
    double aP = 0.0, aN = 0.0, sP = 0.0, sN = 0.0;
    for (int j = 0; j < CHUNK; j++) {
        int m = g_sortidx[base + j];
        float fp = g_F2p[b * MM + m];
        float fn = g_F2n[b * MM + m];
        float w = g_Wh2[(size_t)(b * MM + m) * EE + e];
        aP += (double)fp * w;
        aN += (double)fn * w;
        sP += fp;
        sN += fn;
    }
    g_chP[(b * NCHUNK + c) * EE + e] = (float)aP;
    g_chN[(b * NCHUNK + c) * EE + e] = (float)aN;
    if (e == 0) { g_chPs[b * NCHUNK + c] = (float)sP; g_chNs[b * NCHUNK + c] = (float)sN; }
}

// ---------------- 5b. chunk-level offsets (forward for N, reverse for P) ----------------
__global__ void k_offsets() {
    int b = blockIdx.x, e = threadIdx.x;
    double run = 0.0;
    for (int c = 0; c < NCHUNK; c++) {
        g_offN[(b * NCHUNK + c) * EE + e] = (float)run;
        run += g_chN[(b * NCHUNK + c) * EE + e];
    }
    g_preN[((size_t)b * (MM + 1) + MM) * EE + e] = (float)run;
    double runP = 0.0;
    for (int c = NCHUNK - 1; c >= 0; c--) {
        g_offP[(b * NCHUNK + c) * EE + e] = (float)runP;
        runP += g_chP[(b * NCHUNK + c) * EE + e];
    }
    g_sufP[((size_t)b * (MM + 1) + MM) * EE + e] = 0.f;
    if (e == 0) {
        double r = 0.0;
        for (int c = 0; c < NCHUNK; c++) { g_offNs[b * NCHUNK + c] = (float)r; r += g_chNs[b * NCHUNK + c]; }
        g_preNs[b * (MM + 1) + MM] = (float)r;
        double rp = 0.0;
        for (int c = NCHUNK - 1; c >= 0; c--) { g_offPs[b * NCHUNK + c] = (float)rp; rp += g_chPs[b * NCHUNK + c]; }
        g_sufPs[b * (MM + 1) + MM] = 0.f;
    }
}

// ---------------- 5c. fine-grained prefix (N) and suffix (P) sums ----------------
__global__ void k_scan() {
    int b = blockIdx.y, c = blockIdx.x, e = threadIdx.x;
    int base = b * MM + c * CHUNK;
    double runN  = (double)g_offN[(b * NCHUNK + c) * EE + e];
    double runNs = (double)g_offNs[b * NCHUNK + c];
    for (int j = 0; j < CHUNK; j++) {
        int k = c * CHUNK + j;
        g_preN[((size_t)b * (MM + 1) + k) * EE + e] = (float)runN;
        if (e == 0) g_preNs[b * (MM + 1) + k] = (float)runNs;
        int m = g_sortidx[base + j];
        float fn = g_F2n[b * MM + m];
        float w = g_Wh2[(size_t)(b * MM + m) * EE + e];
        runN += (double)fn * w;
        runNs += fn;
    }
    double runP  = (double)g_offP[(b * NCHUNK + c) * EE + e];
    double runPs = (double)g_offPs[b * NCHUNK + c];
    for (int j = CHUNK - 1; j >= 0; j--) {
        int k = c * CHUNK + j;
        int m = g_sortidx[base + j];
        float fp = g_F2p[b * MM + m];
        float w = g_Wh2[(size_t)(b * MM + m) * EE + e];
        runP += (double)fp * w;
        runPs += fp;
        g_sufP[((size_t)b * (MM + 1) + k) * EE + e] = (float)runP;
        if (e == 0) g_sufPs[b * (MM + 1) + k] = (float)runPs;
    }
}

// ---------------- 6. fused rank + context + probs (8 rows per block) ----------------
__global__ void __launch_bounds__(512) k_rankprobs(float* __restrict__ out_ctx,
                                                   float* __restrict__ out_p) {
    __shared__ int   sk[8];
    __shared__ float sc1[8], sc2[8], skey[8];
    int g = blockIdx.x;            // 0 .. B*N/8 - 1
    int row0 = g * 8;
    int b = row0 >> 11;
    int tid = threadIdx.x;
    if (tid < 8) {
        int row = row0 + tid;
        float key = g_key[row];
        const float* sv = g_sortv + b * MM;
        int lo = 0, hi = MM;       // first index with sv[idx] > key
        while (lo < hi) {
            int mid = (lo + hi) >> 1;
            if (sv[mid] > key) hi = mid; else lo = mid + 1;
        }
        float E1p = g_E1p[row], E1n = g_E1n[row];
        float S = E1p * g_sufPs[b * (MM + 1) + lo] + E1n * g_preNs[b * (MM + 1) + lo];
        float invS = 1.f / S;
        sk[tid] = lo;
        sc1[tid] = E1p * invS;
        sc2[tid] = E1n * invS;
        skey[tid] = key;
    }
    __syncthreads();
    // context: 4 rows per pass, 2 passes
    {
        int e = tid & (EE - 1);
        int rb = tid >> 7;         // 0..3
        #pragma unroll
        for (int it = 0; it < 2; it++) {
            int r = it * 4 + rb;
            int row = row0 + r;
            int k = sk[r];
            float num = sc1[r] * g_sufP[((size_t)b * (MM + 1) + k) * EE + e]
                      + sc2[r] * g_preN[((size_t)b * (MM + 1) + k) * EE + e];
            out_ctx[(size_t)row * EE + e] = num;
        }
    }
    // probs: per-batch vectors held in registers, 8 output rows
    const float4 tv = ((const float4*)(g_att2 + b * MM))[tid];
    const float4 pv = ((const float4*)(g_F2p + b * MM))[tid];
    const float4 nv = ((const float4*)(g_F2n + b * MM))[tid];
    #pragma unroll
    for (int r = 0; r < 8; r++) {
        int row = row0 + r;
        float key = skey[r], c1 = sc1[r], c2 = sc2[r];
        float4 o;
        o.x = (tv.x > key) ? c1 * pv.x : c2 * nv.x;
        o.y = (tv.y > key) ? c1 * pv.y : c2 * nv.y;
        o.z = (tv.z > key) ? c1 * pv.z : c2 * nv.z;
        o.w = (tv.w > key) ? c1 * pv.w : c2 * nv.w;
        ((float4*)(out_p + (size_t)row * MM))[tid] = o;
    }
}

// ---------------- launch ----------------
extern "C" void kernel_launch(void* const* d_in, const int* in_sizes, int n_in,
                              void* d_out, int out_size) {
    const float* in1  = (const float*)d_in[0];   // (8,2048,256)
    const float* in2  = (const float*)d_in[1];   // (8,2048,256)
    const float* mask = (const float*)d_in[2];   // (8,1,2048)
    const float* W1   = (const float*)d_in[3];   // (256,128)
    const float* a1   = (const float*)d_in[4];   // (256,1)
    float* out = (float*)d_out;
    float* out_ctx   = out;                              // (8,2048,128)
    float* out_probs = out + (size_t)BB * NN * EE;       // (8,2048,2048)

    k_v<<<1, 256>>>(W1, a1);
    k_wh2<<<BB * MM / 64, 256>>>(in2, W1, mask, a1);
    k_att1<<<BB * NN / 8, 256>>>(in1);
    k_sort<<<BB, 512>>>();
    dim3 gc(NCHUNK, BB);
    k_chunksum<<<gc, EE>>>();
    k_offsets<<<BB, EE>>>();
    k_scan<<<gc, EE>>>();
    k_rankprobs<<<BB * NN / 8, 512>>>(out_ctx, out_probs);
}